// round 8
// baseline (speedup 1.0000x reference)
#include <cuda_runtime.h>

#define NT 256
#define L_IN 4096
#define DZV 30
#define CV 10
#define NPG 15
#define B_TOT 512

typedef unsigned long long u64;

__constant__ float cWh[DZV*80];   // [d][c][j]
__constant__ float cZ[DZV];

// per-net block of 408 u64, all weights pre-duplicated (w,w):
// [0..96)    conv1: ch*12 + k*4 + oc      (ch<8, k<3, oc<4)
// [96..192)  conv2: 96 + ch*24 + k*8 + oc (ch<4, k<3, oc<8)
// [192..384) conv3: 192 + ch*24 + k*8 + oc (ch<8)
// [384..388) b1d, [388..396) b2d, [396..404) b3d, pad 408
__device__ u64 g_wdup[DZV*408];

__device__ __forceinline__ u64 cat2(float a, float b) {
    union { float2 f; u64 u; } c; c.f = make_float2(a, b); return c.u;
}
__device__ __forceinline__ float2 u2f(u64 v) {
    union { float2 f; u64 u; } c; c.u = v; return c.f;
}
__device__ __forceinline__ u64 ffma2(u64 a, u64 b, u64 c) {
    u64 d; asm("fma.rn.f32x2 %0, %1, %2, %3;" : "=l"(d) : "l"(a), "l"(b), "l"(c)); return d;
}
// 4 oc accumulators, one tap (dup weights in wa=(oc0,oc1), wb=(oc2,oc3))
__device__ __forceinline__ void tap4(u64* acc, u64 t, ulonglong2 wa, ulonglong2 wb) {
    acc[0] = ffma2(wa.x, t, acc[0]);
    acc[1] = ffma2(wa.y, t, acc[1]);
    acc[2] = ffma2(wb.x, t, acc[2]);
    acc[3] = ffma2(wb.y, t, acc[3]);
}
// 8 oc accumulators, one tap (w4 = 4 ulonglong2 = 8 dup weights)
__device__ __forceinline__ void tap8(u64* acc, u64 t, const ulonglong2* w4) {
    acc[0] = ffma2(w4[0].x, t, acc[0]);
    acc[1] = ffma2(w4[0].y, t, acc[1]);
    acc[2] = ffma2(w4[1].x, t, acc[2]);
    acc[3] = ffma2(w4[1].y, t, acc[3]);
    acc[4] = ffma2(w4[2].x, t, acc[4]);
    acc[5] = ffma2(w4[2].y, t, acc[5]);
    acc[6] = ffma2(w4[3].x, t, acc[6]);
    acc[7] = ffma2(w4[3].y, t, acc[7]);
}

__global__ void prep_kernel(const float* __restrict__ W1, const float* __restrict__ b1,
                            const float* __restrict__ W2, const float* __restrict__ b2,
                            const float* __restrict__ W3, const float* __restrict__ b3,
                            const float* __restrict__ z,  const float* __restrict__ bh,
                            float* __restrict__ out) {
    int i = blockIdx.x * blockDim.x + threadIdx.x;
    if (i < DZV*404) {
        int n = i / 404, r = i % 404;
        float v;
        if (r < 96) {
            int ch = r / 12, k = (r % 12) / 4, oc = r & 3;
            v = W1[n*96 + oc*24 + ch*3 + k];
        } else if (r < 192) {
            int t = r - 96, ch = t / 24, k = (t % 24) / 8, oc = t & 7;
            v = W2[n*96 + oc*12 + ch*3 + k];
        } else if (r < 384) {
            int t = r - 192, ch = t / 24, k = (t % 24) / 8, oc = t & 7;
            v = W3[n*192 + oc*24 + ch*3 + k];
        } else if (r < 388) v = b1[n*4 + (r-384)];
        else if (r < 396)   v = b2[n*8 + (r-388)];
        else                v = b3[n*8 + (r-396)];
        g_wdup[n*408 + r] = cat2(v, v);
    }
    if (i < B_TOT*CV) {
        int c = i % CV;
        float s = 0.f;
        #pragma unroll
        for (int d = 0; d < DZV; d++) s = fmaf(z[d], bh[d*CV + c], s);
        out[i] = s;
    }
}

// ---- smem float offsets ----
#define XE_BASE 0           // [8][2056]
#define XO_BASE 16448       // [8][2056]
#define HE_BASE 32896       // [4][1032]
#define HO_BASE 37024       // [4][1032]
#define H2_BASE 41152       // [8][1032]
#define RED_OFF 49408       // [8 warps][8]
#define SMEM_FLOATS 49472   // 197888 B

__global__ __launch_bounds__(NT, 1)
void ensemble_kernel(const int* __restrict__ ids,
                     const float* __restrict__ mask,
                     const float* __restrict__ embed,
                     float* __restrict__ out)
{
    extern __shared__ float sm[];
    float* red = sm + RED_OFF;

    const int tid  = threadIdx.x;
    const int lane = tid & 31;
    const int warp = tid >> 5;
    const int b    = blockIdx.x;
    const int g    = blockIdx.y;

    // ---- zero pads (read only by dead/pad positions) ----
    if (tid < 8)                sm[XE_BASE + tid*2056 + 2048] = 0.f;
    else if (tid < 12)          sm[HE_BASE + (tid-8)*1032 + 1024] = 0.f;
    else if (tid >= 16 && tid < 32)
        sm[H2_BASE + ((tid-16)>>1)*1032 + 1024 + (tid & 1)] = 0.f;

    // ---- gather masked embeddings, channel-major, even/odd deinterleaved ----
    #pragma unroll 1
    for (int i = tid; i < L_IN; i += NT) {
        int   id = __ldg(&ids[b*L_IN + i]);
        float m  = __ldg(&mask[b*L_IN + i]);
        float4 e0 = __ldg((const float4*)(embed + (size_t)id*8));
        float4 e1 = __ldg((const float4*)(embed + (size_t)id*8 + 4));
        int base = ((i & 1) ? XO_BASE : XE_BASE) + (i >> 1);
        sm[base + 0*2056] = e0.x*m; sm[base + 1*2056] = e0.y*m;
        sm[base + 2*2056] = e0.z*m; sm[base + 3*2056] = e0.w*m;
        sm[base + 4*2056] = e1.x*m; sm[base + 5*2056] = e1.y*m;
        sm[base + 6*2056] = e1.z*m; sm[base + 7*2056] = e1.w*m;
    }
    __syncthreads();

    float oacc = 0.f;   // warp0, lane<CV

    #pragma unroll 1
    for (int dn = 0; dn < NPG; dn++) {
        const int d = g*NPG + dn;
        const u64* WB = g_wdup + (size_t)d*408;

        // ======== conv1: K3 S2, 8->4ch, ReLU ========
        // thread: 2 chunks (u = s*256+tid), 2 pos-pairs per chunk, all 4 oc
        {
            u64 acc[2][2][4];   // [chunk][pair][oc]
            {
                ulonglong2 b0 = __ldg((const ulonglong2*)(WB + 384));
                ulonglong2 b1 = __ldg((const ulonglong2*)(WB + 386));
                #pragma unroll
                for (int s = 0; s < 2; s++)
                    #pragma unroll
                    for (int j = 0; j < 2; j++) {
                        acc[s][j][0] = b0.x; acc[s][j][1] = b0.y;
                        acc[s][j][2] = b1.x; acc[s][j][3] = b1.y;
                    }
            }
            #pragma unroll 2
            for (int ch = 0; ch < 8; ch++) {
                const ulonglong2* wp = (const ulonglong2*)(WB + ch*12);
                ulonglong2 w0 = __ldg(wp+0), w1 = __ldg(wp+1);   // tap0 oc01,oc23
                ulonglong2 w2 = __ldg(wp+2), w3 = __ldg(wp+3);   // tap1
                ulonglong2 w4 = __ldg(wp+4), w5 = __ldg(wp+5);   // tap2
                #pragma unroll
                for (int s = 0; s < 2; s++) {
                    const int u = s*NT + tid;
                    const float* XEr = sm + XE_BASE + ch*2056 + 4*u;
                    const float* XOr = sm + XO_BASE + ch*2056 + 4*u;
                    float4 A = *(const float4*)XEr;
                    float  e = XEr[4];
                    float4 C = *(const float4*)XOr;
                    // pair j=0 (m=2u): taps (A.x,A.y) (C.x,C.y) (A.y,A.z)
                    tap4(acc[s][0], cat2(A.x,A.y), w0, w1);
                    tap4(acc[s][0], cat2(C.x,C.y), w2, w3);
                    tap4(acc[s][0], cat2(A.y,A.z), w4, w5);
                    // pair j=1 (m=2u+1): taps (A.z,A.w) (C.z,C.w) (A.w,e)
                    tap4(acc[s][1], cat2(A.z,A.w), w0, w1);
                    tap4(acc[s][1], cat2(C.z,C.w), w2, w3);
                    tap4(acc[s][1], cat2(A.w,e),   w4, w5);
                }
            }
            // stores: HE[m]=lo, HO[m]=hi; m = 2u+j
            #pragma unroll
            for (int s = 0; s < 2; s++) {
                const int u = s*NT + tid;
                #pragma unroll
                for (int oc = 0; oc < 4; oc++) {
                    float2 p0 = u2f(acc[s][0][oc]);
                    float2 p1 = u2f(acc[s][1][oc]);
                    *(float2*)(sm + HE_BASE + oc*1032 + 2*u) =
                        make_float2(fmaxf(p0.x,0.f), fmaxf(p1.x,0.f));
                    *(float2*)(sm + HO_BASE + oc*1032 + 2*u) =
                        make_float2(fmaxf(p0.y,0.f), fmaxf(p1.y,0.f));
                }
            }
        }
        __syncthreads();

        // ======== conv2: K3 S2, 4->8ch, ReLU ========
        // thread: pos q = 4t..4t+3 (2 pairs), all 8 oc
        {
            u64 acc[2][8];
            {
                ulonglong2 b0 = __ldg((const ulonglong2*)(WB + 388));
                ulonglong2 b1 = __ldg((const ulonglong2*)(WB + 390));
                ulonglong2 b2 = __ldg((const ulonglong2*)(WB + 392));
                ulonglong2 b3 = __ldg((const ulonglong2*)(WB + 394));
                #pragma unroll
                for (int j = 0; j < 2; j++) {
                    acc[j][0]=b0.x; acc[j][1]=b0.y; acc[j][2]=b1.x; acc[j][3]=b1.y;
                    acc[j][4]=b2.x; acc[j][5]=b2.y; acc[j][6]=b3.x; acc[j][7]=b3.y;
                }
            }
            #pragma unroll 2
            for (int ch = 0; ch < 4; ch++) {
                const ulonglong2* wp = (const ulonglong2*)(WB + 96 + ch*24);
                ulonglong2 w[12];
                #pragma unroll
                for (int i = 0; i < 12; i++) w[i] = __ldg(wp + i);
                const float* HEr = sm + HE_BASE + ch*1032 + 4*tid;
                const float* HOr = sm + HO_BASE + ch*1032 + 4*tid;
                float4 A = *(const float4*)HEr;
                float  e = HEr[4];
                float4 C = *(const float4*)HOr;
                // pair j=0 (m=2t): taps (A.x,A.y) (C.x,C.y) (A.y,A.z)
                tap8(acc[0], cat2(A.x,A.y), w + 0);
                tap8(acc[0], cat2(C.x,C.y), w + 4);
                tap8(acc[0], cat2(A.y,A.z), w + 8);
                // pair j=1 (m=2t+1): taps (A.z,A.w) (C.z,C.w) (A.w,e)
                tap8(acc[1], cat2(A.z,A.w), w + 0);
                tap8(acc[1], cat2(C.z,C.w), w + 4);
                tap8(acc[1], cat2(A.w,e),   w + 8);
            }
            #pragma unroll
            for (int oc = 0; oc < 8; oc++) {
                float2 p0 = u2f(acc[0][oc]);
                float2 p1 = u2f(acc[1][oc]);
                *(float4*)(sm + H2_BASE + oc*1032 + 4*tid) =
                    make_float4(fmaxf(p0.x,0.f), fmaxf(p0.y,0.f),
                                fmaxf(p1.x,0.f), fmaxf(p1.y,0.f));
            }
        }
        __syncthreads();

        // ======== conv3: K3 S1, 8->8ch, ReLU + pool ========
        // thread: pos p = 4t..4t+3 (2 pairs), all 8 oc
        float psum[8];
        #pragma unroll
        for (int i = 0; i < 8; i++) psum[i] = 0.f;
        {
            u64 acc[2][8];
            {
                ulonglong2 b0 = __ldg((const ulonglong2*)(WB + 396));
                ulonglong2 b1 = __ldg((const ulonglong2*)(WB + 398));
                ulonglong2 b2 = __ldg((const ulonglong2*)(WB + 400));
                ulonglong2 b3 = __ldg((const ulonglong2*)(WB + 402));
                #pragma unroll
                for (int j = 0; j < 2; j++) {
                    acc[j][0]=b0.x; acc[j][1]=b0.y; acc[j][2]=b1.x; acc[j][3]=b1.y;
                    acc[j][4]=b2.x; acc[j][5]=b2.y; acc[j][6]=b3.x; acc[j][7]=b3.y;
                }
            }
            #pragma unroll 2
            for (int ch = 0; ch < 8; ch++) {
                const ulonglong2* wp = (const ulonglong2*)(WB + 192 + ch*24);
                ulonglong2 w[12];
                #pragma unroll
                for (int i = 0; i < 12; i++) w[i] = __ldg(wp + i);
                const float* H2r = sm + H2_BASE + ch*1032 + 4*tid;
                float4 A = *(const float4*)H2r;
                float2 E = *(const float2*)(H2r + 4);
                // pair0 (p,p+1): taps (A.x,A.y) (A.y,A.z) (A.z,A.w)
                tap8(acc[0], cat2(A.x,A.y), w + 0);
                tap8(acc[0], cat2(A.y,A.z), w + 4);
                tap8(acc[0], cat2(A.z,A.w), w + 8);
                // pair1 (p+2,p+3): taps (A.z,A.w) (A.w,E.x) (E.x,E.y)
                tap8(acc[1], cat2(A.z,A.w), w + 0);
                tap8(acc[1], cat2(A.w,E.x), w + 4);
                tap8(acc[1], cat2(E.x,E.y), w + 8);
            }
            const int p = 4*tid;
            const bool v0 = (p     < 1021), v1 = (p + 1 < 1021);
            const bool v2 = (p + 2 < 1021), v3 = (p + 3 < 1021);
            #pragma unroll
            for (int oc = 0; oc < 8; oc++) {
                float2 p0 = u2f(acc[0][oc]);
                float2 p1 = u2f(acc[1][oc]);
                psum[oc] += (v0 ? fmaxf(p0.x,0.f) : 0.f) + (v1 ? fmaxf(p0.y,0.f) : 0.f)
                          + (v2 ? fmaxf(p1.x,0.f) : 0.f) + (v3 ? fmaxf(p1.y,0.f) : 0.f);
            }
        }

        // ---- warp reduce psum -> red[warp][oc] ----
        #pragma unroll
        for (int oc = 0; oc < 8; oc++) {
            float s = psum[oc];
            #pragma unroll
            for (int off = 16; off > 0; off >>= 1)
                s += __shfl_down_sync(0xFFFFFFFFu, s, off);
            if (lane == 0) red[warp*8 + oc] = s;
        }
        __syncthreads();

        // ---- warp0: cross-warp reduce (8 warps) + head matvec ----
        if (warp == 0) {
            float s = red[lane] + red[lane + 32];
            s += __shfl_xor_sync(0xFFFFFFFFu, s, 8);
            s += __shfl_xor_sync(0xFFFFFFFFu, s, 16);
            float pj[8];
            #pragma unroll
            for (int j = 0; j < 8; j++)
                pj[j] = __shfl_sync(0xFFFFFFFFu, s, j);
            if (lane < CV) {
                float v = 0.f;
                #pragma unroll
                for (int j = 0; j < 8; j++)
                    v = fmaf(pj[j], cWh[(d*CV + lane)*8 + j], v);
                oacc = fmaf(v, cZ[d] * (1.0f/1021.0f), oacc);
            }
        }
        // red hazard: next red-write only after conv1/conv2 syncs of next net,
        // which warp0 must also pass after its read above.
    }

    if (warp == 0 && lane < CV)
        atomicAdd(&out[b*CV + lane], oacc);
}

extern "C" void kernel_launch(void* const* d_in, const int* in_sizes, int n_in,
                              void* d_out, int out_size) {
    const int*   ids  = (const int*)  d_in[0];
    const float* mask = (const float*)d_in[1];
    const float* z    = (const float*)d_in[2];
    const float* emb  = (const float*)d_in[3];
    const float* W1   = (const float*)d_in[4];
    const float* b1   = (const float*)d_in[5];
    const float* W2   = (const float*)d_in[6];
    const float* b2   = (const float*)d_in[7];
    const float* W3   = (const float*)d_in[8];
    const float* b3   = (const float*)d_in[9];
    const float* Wh   = (const float*)d_in[10];
    const float* bh   = (const float*)d_in[11];
    float* out = (float*)d_out;

    cudaMemcpyToSymbolAsync(cWh, Wh, DZV*80*sizeof(float), 0, cudaMemcpyDeviceToDevice, 0);
    cudaMemcpyToSymbolAsync(cZ,  z,  DZV*sizeof(float),    0, cudaMemcpyDeviceToDevice, 0);

    prep_kernel<<<(DZV*404 + 255)/256, 256>>>(W1, b1, W2, b2, W3, b3, z, bh, out);

    cudaFuncSetAttribute(ensemble_kernel,
                         cudaFuncAttributeMaxDynamicSharedMemorySize,
                         SMEM_FLOATS * (int)sizeof(float));
    ensemble_kernel<<<dim3(B_TOT, 2), NT, SMEM_FLOATS * (int)sizeof(float)>>>(ids, mask, emb, out);
}

// round 9
// speedup vs baseline: 1.4745x; 1.4745x over previous
#include <cuda_runtime.h>

#define NT 256
#define L_IN 4096
#define DZV 30
#define CV 10
#define NPG 15
#define B_TOT 512

typedef unsigned long long u64;

__constant__ float cWh[DZV*80];   // [d][c][j]
__constant__ float cZ[DZV];

// per-net block of 408 u64, all weights pre-duplicated (w,w):
// [0..96)    conv1: ch*12 + k*4 + oc      (ch<8, k<3, oc<4)
// [96..192)  conv2: 96 + ch*24 + k*8 + oc (ch<4, k<3, oc<8)
// [192..384) conv3: 192 + ch*24 + k*8 + oc (ch<8)
// [384..388) b1d, [388..396) b2d, [396..404) b3d, pad 408
__device__ u64 g_wdup[DZV*408];

__device__ __forceinline__ u64 cat2(float a, float b) {
    union { float2 f; u64 u; } c; c.f = make_float2(a, b); return c.u;
}
__device__ __forceinline__ float2 u2f(u64 v) {
    union { float2 f; u64 u; } c; c.u = v; return c.f;
}
__device__ __forceinline__ u64 ffma2(u64 a, u64 b, u64 c) {
    u64 d; asm("fma.rn.f32x2 %0, %1, %2, %3;" : "=l"(d) : "l"(a), "l"(b), "l"(c)); return d;
}
__device__ __forceinline__ void tap4(u64* acc, u64 t, ulonglong2 wa, ulonglong2 wb) {
    acc[0] = ffma2(wa.x, t, acc[0]);
    acc[1] = ffma2(wa.y, t, acc[1]);
    acc[2] = ffma2(wb.x, t, acc[2]);
    acc[3] = ffma2(wb.y, t, acc[3]);
}
__device__ __forceinline__ void tap8(u64* acc, u64 t, const ulonglong2* w4) {
    acc[0] = ffma2(w4[0].x, t, acc[0]);
    acc[1] = ffma2(w4[0].y, t, acc[1]);
    acc[2] = ffma2(w4[1].x, t, acc[2]);
    acc[3] = ffma2(w4[1].y, t, acc[3]);
    acc[4] = ffma2(w4[2].x, t, acc[4]);
    acc[5] = ffma2(w4[2].y, t, acc[5]);
    acc[6] = ffma2(w4[3].x, t, acc[6]);
    acc[7] = ffma2(w4[3].y, t, acc[7]);
}

__global__ void prep_kernel(const float* __restrict__ W1, const float* __restrict__ b1,
                            const float* __restrict__ W2, const float* __restrict__ b2,
                            const float* __restrict__ W3, const float* __restrict__ b3,
                            const float* __restrict__ z,  const float* __restrict__ bh,
                            float* __restrict__ out) {
    int i = blockIdx.x * blockDim.x + threadIdx.x;
    if (i < DZV*404) {
        int n = i / 404, r = i % 404;
        float v;
        if (r < 96) {
            int ch = r / 12, k = (r % 12) / 4, oc = r & 3;
            v = W1[n*96 + oc*24 + ch*3 + k];
        } else if (r < 192) {
            int t = r - 96, ch = t / 24, k = (t % 24) / 8, oc = t & 7;
            v = W2[n*96 + oc*12 + ch*3 + k];
        } else if (r < 384) {
            int t = r - 192, ch = t / 24, k = (t % 24) / 8, oc = t & 7;
            v = W3[n*192 + oc*24 + ch*3 + k];
        } else if (r < 388) v = b1[n*4 + (r-384)];
        else if (r < 396)   v = b2[n*8 + (r-388)];
        else                v = b3[n*8 + (r-396)];
        g_wdup[n*408 + r] = cat2(v, v);
    }
    if (i < B_TOT*CV) {
        int c = i % CV;
        float s = 0.f;
        #pragma unroll
        for (int d = 0; d < DZV; d++) s = fmaf(z[d], bh[d*CV + c], s);
        out[i] = s;
    }
}

// ---- smem float offsets ----
#define XE_BASE 0           // [8][2056]
#define XO_BASE 16448       // [8][2056]
#define HE_BASE 32896       // [4][1032]
#define HO_BASE 37024       // [4][1032]
#define H2_BASE 41152       // [8][1032]
#define RED_OFF 49408       // [8 warps][8]
#define WS_OFF  49472       // 2 x 816 floats (ping-pong weight buffers, 16B aligned)
#define SMEM_FLOATS 51104   // 204416 B

__global__ __launch_bounds__(NT, 1)
void ensemble_kernel(const int* __restrict__ ids,
                     const float* __restrict__ mask,
                     const float* __restrict__ embed,
                     float* __restrict__ out)
{
    extern __shared__ float sm[];
    float* red = sm + RED_OFF;

    const int tid  = threadIdx.x;
    const int lane = tid & 31;
    const int warp = tid >> 5;
    const int b    = blockIdx.x;
    const int g    = blockIdx.y;

    // ---- zero pads (read only by dead/pad positions) ----
    if (tid < 8)                sm[XE_BASE + tid*2056 + 2048] = 0.f;
    else if (tid < 12)          sm[HE_BASE + (tid-8)*1032 + 1024] = 0.f;
    else if (tid >= 16 && tid < 32)
        sm[H2_BASE + ((tid-16)>>1)*1032 + 1024 + (tid & 1)] = 0.f;

    // ---- stage first net's weight block into buffer 0 ----
    if (tid < 204)
        ((float4*)(sm + WS_OFF))[tid] =
            __ldg((const float4*)(g_wdup + (size_t)(g*NPG)*408) + tid);

    // ---- gather masked embeddings, channel-major, even/odd deinterleaved ----
    #pragma unroll 1
    for (int i = tid; i < L_IN; i += NT) {
        int   id = __ldg(&ids[b*L_IN + i]);
        float m  = __ldg(&mask[b*L_IN + i]);
        float4 e0 = __ldg((const float4*)(embed + (size_t)id*8));
        float4 e1 = __ldg((const float4*)(embed + (size_t)id*8 + 4));
        int base = ((i & 1) ? XO_BASE : XE_BASE) + (i >> 1);
        sm[base + 0*2056] = e0.x*m; sm[base + 1*2056] = e0.y*m;
        sm[base + 2*2056] = e0.z*m; sm[base + 3*2056] = e0.w*m;
        sm[base + 4*2056] = e1.x*m; sm[base + 5*2056] = e1.y*m;
        sm[base + 6*2056] = e1.z*m; sm[base + 7*2056] = e1.w*m;
    }
    __syncthreads();

    float oacc = 0.f;   // warp0, lane<CV

    #pragma unroll 1
    for (int dn = 0; dn < NPG; dn++) {
        const int d = g*NPG + dn;
        // this net's weights: smem ping-pong buffer, ulonglong2 units
        const ulonglong2* WQ = (const ulonglong2*)(sm + WS_OFF + (dn & 1)*816);

        // ======== conv1: K3 S2, 8->4ch, ReLU ========
        // thread: 2 chunks (u = s*256+tid), 2 pos-pairs per chunk, all 4 oc
        {
            u64 acc[2][2][4];   // [chunk][pair][oc]
            {
                ulonglong2 b0 = WQ[192], b1 = WQ[193];
                #pragma unroll
                for (int s = 0; s < 2; s++)
                    #pragma unroll
                    for (int j = 0; j < 2; j++) {
                        acc[s][j][0] = b0.x; acc[s][j][1] = b0.y;
                        acc[s][j][2] = b1.x; acc[s][j][3] = b1.y;
                    }
            }
            #pragma unroll 2
            for (int ch = 0; ch < 8; ch++) {
                const ulonglong2* wp = WQ + ch*6;
                ulonglong2 w0 = wp[0], w1 = wp[1];   // tap0 oc01,oc23
                ulonglong2 w2 = wp[2], w3 = wp[3];   // tap1
                ulonglong2 w4 = wp[4], w5 = wp[5];   // tap2
                #pragma unroll
                for (int s = 0; s < 2; s++) {
                    const int u = s*NT + tid;
                    const float* XEr = sm + XE_BASE + ch*2056 + 4*u;
                    const float* XOr = sm + XO_BASE + ch*2056 + 4*u;
                    float4 A = *(const float4*)XEr;
                    float  e = XEr[4];
                    float4 C = *(const float4*)XOr;
                    // pair j=0 (m=2u): taps (A.x,A.y) (C.x,C.y) (A.y,A.z)
                    tap4(acc[s][0], cat2(A.x,A.y), w0, w1);
                    tap4(acc[s][0], cat2(C.x,C.y), w2, w3);
                    tap4(acc[s][0], cat2(A.y,A.z), w4, w5);
                    // pair j=1 (m=2u+1): taps (A.z,A.w) (C.z,C.w) (A.w,e)
                    tap4(acc[s][1], cat2(A.z,A.w), w0, w1);
                    tap4(acc[s][1], cat2(C.z,C.w), w2, w3);
                    tap4(acc[s][1], cat2(A.w,e),   w4, w5);
                }
            }
            // stores: HE[m]=lo half (even pos), HO[m]=hi half (odd pos); m=2u+j
            #pragma unroll
            for (int s = 0; s < 2; s++) {
                const int u = s*NT + tid;
                #pragma unroll
                for (int oc = 0; oc < 4; oc++) {
                    float2 p0 = u2f(acc[s][0][oc]);
                    float2 p1 = u2f(acc[s][1][oc]);
                    *(float2*)(sm + HE_BASE + oc*1032 + 2*u) =
                        make_float2(fmaxf(p0.x,0.f), fmaxf(p1.x,0.f));
                    *(float2*)(sm + HO_BASE + oc*1032 + 2*u) =
                        make_float2(fmaxf(p0.y,0.f), fmaxf(p1.y,0.f));
                }
            }
        }
        __syncthreads();

        // ---- stage NEXT net's weights into the other buffer (hidden under conv2/3).
        // Safe: other buffer last read in conv3 of net dn-1, which all threads
        // completed before this barrier; consumers of the staged data run after
        // the post-reduce barrier below.
        if (dn + 1 < NPG && tid < 204)
            ((float4*)(sm + WS_OFF + ((dn+1) & 1)*816))[tid] =
                __ldg((const float4*)(g_wdup + (size_t)(d+1)*408) + tid);

        // ======== conv2: K3 S2, 4->8ch, ReLU ========
        // thread: pos q = 4t..4t+3 (2 pairs), all 8 oc
        {
            u64 acc[2][8];
            {
                ulonglong2 b0 = WQ[194], b1 = WQ[195];
                ulonglong2 b2 = WQ[196], b3 = WQ[197];
                #pragma unroll
                for (int j = 0; j < 2; j++) {
                    acc[j][0]=b0.x; acc[j][1]=b0.y; acc[j][2]=b1.x; acc[j][3]=b1.y;
                    acc[j][4]=b2.x; acc[j][5]=b2.y; acc[j][6]=b3.x; acc[j][7]=b3.y;
                }
            }
            #pragma unroll
            for (int ch = 0; ch < 4; ch++) {
                const ulonglong2* wp = WQ + 48 + ch*12;
                ulonglong2 w[12];
                #pragma unroll
                for (int i = 0; i < 12; i++) w[i] = wp[i];
                const float* HEr = sm + HE_BASE + ch*1032 + 4*tid;
                const float* HOr = sm + HO_BASE + ch*1032 + 4*tid;
                float4 A = *(const float4*)HEr;
                float  e = HEr[4];
                float4 C = *(const float4*)HOr;
                // pair j=0 (m=2t): taps (A.x,A.y) (C.x,C.y) (A.y,A.z)
                tap8(acc[0], cat2(A.x,A.y), w + 0);
                tap8(acc[0], cat2(C.x,C.y), w + 4);
                tap8(acc[0], cat2(A.y,A.z), w + 8);
                // pair j=1 (m=2t+1): taps (A.z,A.w) (C.z,C.w) (A.w,e)
                tap8(acc[1], cat2(A.z,A.w), w + 0);
                tap8(acc[1], cat2(C.z,C.w), w + 4);
                tap8(acc[1], cat2(A.w,e),   w + 8);
            }
            #pragma unroll
            for (int oc = 0; oc < 8; oc++) {
                float2 p0 = u2f(acc[0][oc]);
                float2 p1 = u2f(acc[1][oc]);
                *(float4*)(sm + H2_BASE + oc*1032 + 4*tid) =
                    make_float4(fmaxf(p0.x,0.f), fmaxf(p0.y,0.f),
                                fmaxf(p1.x,0.f), fmaxf(p1.y,0.f));
            }
        }
        __syncthreads();

        // ======== conv3: K3 S1, 8->8ch, ReLU + pool ========
        // thread: pos p = 4t..4t+3 (2 pairs), all 8 oc; valid p < 1021
        float psum[8];
        #pragma unroll
        for (int i = 0; i < 8; i++) psum[i] = 0.f;
        {
            u64 acc[2][8];
            {
                ulonglong2 b0 = WQ[198], b1 = WQ[199];
                ulonglong2 b2 = WQ[200], b3 = WQ[201];
                #pragma unroll
                for (int j = 0; j < 2; j++) {
                    acc[j][0]=b0.x; acc[j][1]=b0.y; acc[j][2]=b1.x; acc[j][3]=b1.y;
                    acc[j][4]=b2.x; acc[j][5]=b2.y; acc[j][6]=b3.x; acc[j][7]=b3.y;
                }
            }
            #pragma unroll 2
            for (int ch = 0; ch < 8; ch++) {
                const ulonglong2* wp = WQ + 96 + ch*12;
                ulonglong2 w[12];
                #pragma unroll
                for (int i = 0; i < 12; i++) w[i] = wp[i];
                const float* H2r = sm + H2_BASE + ch*1032 + 4*tid;
                float4 A = *(const float4*)H2r;
                float2 E = *(const float2*)(H2r + 4);
                // pair0 (p,p+1): taps (A.x,A.y) (A.y,A.z) (A.z,A.w)
                tap8(acc[0], cat2(A.x,A.y), w + 0);
                tap8(acc[0], cat2(A.y,A.z), w + 4);
                tap8(acc[0], cat2(A.z,A.w), w + 8);
                // pair1 (p+2,p+3): taps (A.z,A.w) (A.w,E.x) (E.x,E.y)
                tap8(acc[1], cat2(A.z,A.w), w + 0);
                tap8(acc[1], cat2(A.w,E.x), w + 4);
                tap8(acc[1], cat2(E.x,E.y), w + 8);
            }
            const int p = 4*tid;
            const bool v0 = (p     < 1021), v1 = (p + 1 < 1021);
            const bool v2 = (p + 2 < 1021), v3 = (p + 3 < 1021);
            #pragma unroll
            for (int oc = 0; oc < 8; oc++) {
                float2 p0 = u2f(acc[0][oc]);
                float2 p1 = u2f(acc[1][oc]);
                psum[oc] += (v0 ? fmaxf(p0.x,0.f) : 0.f) + (v1 ? fmaxf(p0.y,0.f) : 0.f)
                          + (v2 ? fmaxf(p1.x,0.f) : 0.f) + (v3 ? fmaxf(p1.y,0.f) : 0.f);
            }
        }

        // ---- warp reduce psum -> red[warp][oc] ----
        #pragma unroll
        for (int oc = 0; oc < 8; oc++) {
            float s = psum[oc];
            #pragma unroll
            for (int off = 16; off > 0; off >>= 1)
                s += __shfl_down_sync(0xFFFFFFFFu, s, off);
            if (lane == 0) red[warp*8 + oc] = s;
        }
        __syncthreads();

        // ---- warp0: cross-warp reduce (8 warps) + head matvec ----
        if (warp == 0) {
            float s = red[lane] + red[lane + 32];
            s += __shfl_xor_sync(0xFFFFFFFFu, s, 8);
            s += __shfl_xor_sync(0xFFFFFFFFu, s, 16);
            float pj[8];
            #pragma unroll
            for (int j = 0; j < 8; j++)
                pj[j] = __shfl_sync(0xFFFFFFFFu, s, j);
            if (lane < CV) {
                float v = 0.f;
                #pragma unroll
                for (int j = 0; j < 8; j++)
                    v = fmaf(pj[j], cWh[(d*CV + lane)*8 + j], v);
                oacc = fmaf(v, cZ[d] * (1.0f/1021.0f), oacc);
            }
        }
        // red hazard: next red-write only after conv1/conv2 syncs of next net,
        // which warp0 must also pass after its read above.
    }

    if (warp == 0 && lane < CV)
        atomicAdd(&out[b*CV + lane], oacc);
}

extern "C" void kernel_launch(void* const* d_in, const int* in_sizes, int n_in,
                              void* d_out, int out_size) {
    const int*   ids  = (const int*)  d_in[0];
    const float* mask = (const float*)d_in[1];
    const float* z    = (const float*)d_in[2];
    const float* emb  = (const float*)d_in[3];
    const float* W1   = (const float*)d_in[4];
    const float* b1   = (const float*)d_in[5];
    const float* W2   = (const float*)d_in[6];
    const float* b2   = (const float*)d_in[7];
    const float* W3   = (const float*)d_in[8];
    const float* b3   = (const float*)d_in[9];
    const float* Wh   = (const float*)d_in[10];
    const float* bh   = (const float*)d_in[11];
    float* out = (float*)d_out;

    cudaMemcpyToSymbolAsync(cWh, Wh, DZV*80*sizeof(float), 0, cudaMemcpyDeviceToDevice, 0);
    cudaMemcpyToSymbolAsync(cZ,  z,  DZV*sizeof(float),    0, cudaMemcpyDeviceToDevice, 0);

    prep_kernel<<<(DZV*404 + 255)/256, 256>>>(W1, b1, W2, b2, W3, b3, z, bh, out);

    cudaFuncSetAttribute(ensemble_kernel,
                         cudaFuncAttributeMaxDynamicSharedMemorySize,
                         SMEM_FLOATS * (int)sizeof(float));
    ensemble_kernel<<<dim3(B_TOT, 2), NT, SMEM_FLOATS * (int)sizeof(float)>>>(ids, mask, emb, out);
}